// round 13
// baseline (speedup 1.0000x reference)
#include <cuda_runtime.h>
#include <cstdint>

// Problem constants (match reference_code)
#define N0c 200000
#define N1c 50000
#define N2c 12500
#define N3c 3200
#define E0c 500000
#define E1c 125000
#define E2c 32000
#define DINc 128
#define DHc 256
#define DOUTc 128

// ---------------- scratch (static device globals; no allocations) ----------------
__device__ float g_mean[(size_t)N1c * DHc];
__device__ float g_h1[(size_t)N1c * DHc];
__device__ float g_h2[(size_t)N2c * DHc];
__device__ int g_deg0[N1c]; __device__ int g_off0[N1c + 1]; __device__ int g_cur0[N1c]; __device__ int g_esrc0[E0c];
__device__ int g_deg1[N2c]; __device__ int g_off1[N2c + 1]; __device__ int g_cur1[N2c]; __device__ int g_esrc1[E1c];
__device__ int g_deg2[N3c]; __device__ int g_off2[N3c + 1]; __device__ int g_cur2[N3c]; __device__ int g_esrc2[E2c];
__device__ int g_done;   // last-block ticket (reset by the scan block each run)

// ---------------- fused hist + scan (last-block-done pattern) ----------------
// Grid-wide histogram into deg, then the LAST block to finish performs the
// exclusive scan into off/cur, re-zeroing deg for the next invocation
// (module-load zero-init covers the first) and resetting the ticket.
__global__ void histscan_k(const int* __restrict__ dst, int* deg,
                           int* off, int* cur, int n, int E) {
    int e = blockIdx.x * blockDim.x + threadIdx.x;
    if (e < E) atomicAdd(&deg[dst[e]], 1);
    __threadfence();

    __shared__ bool isLast;
    if (threadIdx.x == 0) {
        int d = atomicAdd(&g_done, 1);
        isLast = (d == (int)gridDim.x - 1);
    }
    __syncthreads();
    if (!isLast) return;

    // ---- this single block (256 threads) scans deg[0..n) ----
    const int T = 256;
    __shared__ int wsum[8];
    int tid = threadIdx.x, lane = tid & 31, wid = tid >> 5;
    int chunk = (n + T - 1) / T;
    int beg = min(tid * chunk, n), end = min(beg + chunk, n);

    int sum = 0;
    for (int i = beg; i < end; i++) sum += deg[i];

    int s = sum;
    #pragma unroll
    for (int o = 1; o < 32; o <<= 1) {
        int t = __shfl_up_sync(0xffffffffu, s, o);
        if (lane >= o) s += t;
    }
    if (lane == 31) wsum[wid] = s;
    __syncthreads();
    if (wid == 0 && lane < 8) {
        int ws = wsum[lane];
        #pragma unroll
        for (int o = 1; o < 8; o <<= 1) {
            int t = __shfl_up_sync(0xffu, ws, o);
            if (lane >= o) ws += t;
        }
        wsum[lane] = ws;
    }
    __syncthreads();
    int excl = s - sum + ((wid > 0) ? wsum[wid - 1] : 0);

    int run = excl;
    for (int i = beg; i < end; i++) {
        int d = deg[i];
        off[i] = run;
        cur[i] = run;
        run += d;
        deg[i] = 0;                       // ready for next invocation
    }
    if (tid == 0) {
        off[n] = E;
        g_done = 0;                       // reset ticket (deterministic replays)
    }
}

__global__ void bucket_k(const int* __restrict__ src, const int* __restrict__ dst,
                         int* cur, int* esrc, int E) {
    int e = blockIdx.x * blockDim.x + threadIdx.x;
    if (e < E) {
        int p = atomicAdd(&cur[dst[e]], 1);
        esrc[p] = src[e];
    }
}

// ---------------- aggregation: warp per target node (R2 version, 2-edge unroll) ----------------
template <int D>
__global__ void aggregate_kernel(const float* __restrict__ X, float* __restrict__ mean,
                                 const int* __restrict__ off, const int* __restrict__ esrc,
                                 int n_tgt) {
    int w = (blockIdx.x * blockDim.x + threadIdx.x) >> 5;
    int lane = threadIdx.x & 31;
    if (w >= n_tgt) return;
    int beg = off[w], end = off[w + 1];
    float acc[D / 32];
    #pragma unroll
    for (int i = 0; i < D / 32; i++) acc[i] = 0.f;
    int e = beg;
    for (; e + 1 < end; e += 2) {
        int s0 = esrc[e], s1 = esrc[e + 1];
        const float4* r0 = (const float4*)(X + (size_t)s0 * D);
        const float4* r1 = (const float4*)(X + (size_t)s1 * D);
        #pragma unroll
        for (int i = 0; i < D / 128; i++) {
            float4 v0 = r0[lane + 32 * i];
            float4 v1 = r1[lane + 32 * i];
            acc[4 * i + 0] += v0.x + v1.x;
            acc[4 * i + 1] += v0.y + v1.y;
            acc[4 * i + 2] += v0.z + v1.z;
            acc[4 * i + 3] += v0.w + v1.w;
        }
    }
    if (e < end) {
        const float4* row = (const float4*)(X + (size_t)esrc[e] * D);
        #pragma unroll
        for (int i = 0; i < D / 128; i++) {
            float4 v = row[lane + 32 * i];
            acc[4 * i + 0] += v.x;
            acc[4 * i + 1] += v.y;
            acc[4 * i + 2] += v.z;
            acc[4 * i + 3] += v.w;
        }
    }
    float inv = 1.f / (float)max(end - beg, 1);
    float4* mrow = (float4*)(mean + (size_t)w * D);
    #pragma unroll
    for (int i = 0; i < D / 128; i++) {
        float4 o;
        o.x = acc[4 * i + 0] * inv;
        o.y = acc[4 * i + 1] * inv;
        o.z = acc[4 * i + 2] * inv;
        o.w = acc[4 * i + 3] * inv;
        mrow[lane + 32 * i] = o;
    }
}

// ---------------- R2 tf32 GEMM (proven schedule, unchanged) ----------------
__device__ __forceinline__ uint32_t f2tf32(float f) {
    uint32_t u;
    asm("cvt.rna.tf32.f32 %0, %1;" : "=r"(u) : "f"(f));
    return u;
}

#define LDS_ 36

__global__ void __launch_bounds__(256) sage_gemm_tf32(
    const float* __restrict__ A0, const float* __restrict__ A1,
    const float* __restrict__ Wl, const float* __restrict__ Wr,
    const float* __restrict__ bias, float* __restrict__ out,
    int M, int N, int D, int relu)
{
    __shared__ uint32_t As[128 * LDS_];
    __shared__ uint32_t Bs[128 * LDS_];

    int tid = threadIdx.x;
    int lane = tid & 31, wid = tid >> 5;
    int wm = wid & 1;
    int wn = wid >> 1;
    int g = lane >> 2, t = lane & 3;

    int rowBase = blockIdx.x * 128, colBase = blockIdx.y * 128;

    float acc[4][4][4];
    #pragma unroll
    for (int i = 0; i < 4; i++)
        #pragma unroll
        for (int j = 0; j < 4; j++)
            #pragma unroll
            for (int r = 0; r < 4; r++) acc[i][j][r] = 0.f;

    int ldr = tid >> 3;
    int ldc = (tid & 7) * 4;

    for (int kt = 0; kt < 2 * D; kt += 32) {
        const float* A = (kt < D) ? A0 : A1;
        const float* W = (kt < D) ? Wl : Wr;
        int kk = (kt < D) ? kt : (kt - D);

        #pragma unroll
        for (int s = 0; s < 4; s++) {
            int r = ldr + s * 32;
            int grow = rowBase + r;
            float4 v = make_float4(0.f, 0.f, 0.f, 0.f);
            if (grow < M) v = *(const float4*)(A + (size_t)grow * D + kk + ldc);
            uint4 ua;
            ua.x = f2tf32(v.x); ua.y = f2tf32(v.y); ua.z = f2tf32(v.z); ua.w = f2tf32(v.w);
            *(uint4*)&As[r * LDS_ + ldc] = ua;
            float4 w = *(const float4*)(W + (size_t)(colBase + r) * D + kk + ldc);
            uint4 ub;
            ub.x = f2tf32(w.x); ub.y = f2tf32(w.y); ub.z = f2tf32(w.z); ub.w = f2tf32(w.w);
            *(uint4*)&Bs[r * LDS_ + ldc] = ub;
        }
        __syncthreads();

        #pragma unroll
        for (int ks = 0; ks < 32; ks += 8) {
            uint32_t af[4][4];
            #pragma unroll
            for (int mi = 0; mi < 4; mi++) {
                int m = wm * 64 + mi * 16;
                af[mi][0] = As[(m + g)     * LDS_ + ks + t];
                af[mi][1] = As[(m + g + 8) * LDS_ + ks + t];
                af[mi][2] = As[(m + g)     * LDS_ + ks + t + 4];
                af[mi][3] = As[(m + g + 8) * LDS_ + ks + t + 4];
            }
            uint32_t bf[4][2];
            #pragma unroll
            for (int ni = 0; ni < 4; ni++) {
                int n = wn * 32 + ni * 8;
                bf[ni][0] = Bs[(n + g) * LDS_ + ks + t];
                bf[ni][1] = Bs[(n + g) * LDS_ + ks + t + 4];
            }
            #pragma unroll
            for (int mi = 0; mi < 4; mi++)
                #pragma unroll
                for (int ni = 0; ni < 4; ni++) {
                    asm volatile(
                        "mma.sync.aligned.m16n8k8.row.col.f32.tf32.tf32.f32 "
                        "{%0,%1,%2,%3}, {%4,%5,%6,%7}, {%8,%9}, {%0,%1,%2,%3};"
                        : "+f"(acc[mi][ni][0]), "+f"(acc[mi][ni][1]),
                          "+f"(acc[mi][ni][2]), "+f"(acc[mi][ni][3])
                        : "r"(af[mi][0]), "r"(af[mi][1]), "r"(af[mi][2]), "r"(af[mi][3]),
                          "r"(bf[ni][0]), "r"(bf[ni][1]));
                }
        }
        __syncthreads();
    }

    #pragma unroll
    for (int mi = 0; mi < 4; mi++) {
        #pragma unroll
        for (int ni = 0; ni < 4; ni++) {
            int col = colBase + wn * 32 + ni * 8 + t * 2;
            float b0v = bias[col], b1v = bias[col + 1];
            int row0 = rowBase + wm * 64 + mi * 16 + g;
            if (row0 < M) {
                float2 o;
                o.x = acc[mi][ni][0] + b0v;
                o.y = acc[mi][ni][1] + b1v;
                if (relu) { o.x = fmaxf(o.x, 0.f); o.y = fmaxf(o.y, 0.f); }
                *(float2*)(out + (size_t)row0 * N + col) = o;
            }
            int row1 = row0 + 8;
            if (row1 < M) {
                float2 o;
                o.x = acc[mi][ni][2] + b0v;
                o.y = acc[mi][ni][3] + b1v;
                if (relu) { o.x = fmaxf(o.x, 0.f); o.y = fmaxf(o.y, 0.f); }
                *(float2*)(out + (size_t)row1 * N + col) = o;
            }
        }
    }
}

extern "C" void kernel_launch(void* const* d_in, const int* in_sizes, int n_in,
                              void* d_out, int out_size)
{
    const float* x    = (const float*)d_in[0];
    const int*   src0 = (const int*)d_in[1];
    const int*   dst0 = (const int*)d_in[2];
    const int*   src1 = (const int*)d_in[3];
    const int*   dst1 = (const int*)d_in[4];
    const int*   src2 = (const int*)d_in[5];
    const int*   dst2 = (const int*)d_in[6];
    const float* wl0  = (const float*)d_in[7];
    const float* wr0  = (const float*)d_in[8];
    const float* b0   = (const float*)d_in[9];
    const float* wl1  = (const float*)d_in[10];
    const float* wr1  = (const float*)d_in[11];
    const float* b1   = (const float*)d_in[12];
    const float* wl2  = (const float*)d_in[13];
    const float* wr2  = (const float*)d_in[14];
    const float* b2   = (const float*)d_in[15];
    float* out = (float*)d_out;

    float *h1, *h2, *mean;
    cudaGetSymbolAddress((void**)&h1, g_h1);
    cudaGetSymbolAddress((void**)&h2, g_h2);
    cudaGetSymbolAddress((void**)&mean, g_mean);
    int *deg0, *off0, *cur0, *es0, *deg1, *off1, *cur1, *es1, *deg2, *off2, *cur2, *es2;
    cudaGetSymbolAddress((void**)&deg0, g_deg0);
    cudaGetSymbolAddress((void**)&off0, g_off0);
    cudaGetSymbolAddress((void**)&cur0, g_cur0);
    cudaGetSymbolAddress((void**)&es0, g_esrc0);
    cudaGetSymbolAddress((void**)&deg1, g_deg1);
    cudaGetSymbolAddress((void**)&off1, g_off1);
    cudaGetSymbolAddress((void**)&cur1, g_cur1);
    cudaGetSymbolAddress((void**)&es1, g_esrc1);
    cudaGetSymbolAddress((void**)&deg2, g_deg2);
    cudaGetSymbolAddress((void**)&off2, g_off2);
    cudaGetSymbolAddress((void**)&cur2, g_cur2);
    cudaGetSymbolAddress((void**)&es2, g_esrc2);

    // Serial single stream (R2 structure). Launch order:
    // histscan0(1) bucket0(2) agg0(3) gemm0(4) <- ncu profiles gemm0
    histscan_k<<<(E0c + 255) / 256, 256>>>(dst0, deg0, off0, cur0, N1c, E0c);
    bucket_k<<<(E0c + 255) / 256, 256>>>(src0, dst0, cur0, es0, E0c);
    aggregate_kernel<128><<<(N1c * 32 + 255) / 256, 256>>>(x, mean, off0, es0, N1c);
    dim3 g0((N1c + 127) / 128, 2);
    sage_gemm_tf32<<<g0, 256>>>(mean, x, wl0, wr0, b0, h1, N1c, DHc, DINc, 1);

    // Layer 1
    histscan_k<<<(E1c + 255) / 256, 256>>>(dst1, deg1, off1, cur1, N2c, E1c);
    bucket_k<<<(E1c + 255) / 256, 256>>>(src1, dst1, cur1, es1, E1c);
    aggregate_kernel<256><<<(N2c * 32 + 255) / 256, 256>>>(h1, mean, off1, es1, N2c);
    dim3 g1((N2c + 127) / 128, 2);
    sage_gemm_tf32<<<g1, 256>>>(mean, h1, wl1, wr1, b1, h2, N2c, DHc, DHc, 1);

    // Layer 2
    histscan_k<<<(E2c + 255) / 256, 256>>>(dst2, deg2, off2, cur2, N3c, E2c);
    bucket_k<<<(E2c + 255) / 256, 256>>>(src2, dst2, cur2, es2, E2c);
    aggregate_kernel<256><<<(N3c * 32 + 255) / 256, 256>>>(h2, mean, off2, es2, N3c);
    dim3 g2((N3c + 127) / 128, 1);
    sage_gemm_tf32<<<g2, 256>>>(mean, h2, wl2, wr2, b2, out, N3c, DOUTc, DHc, 0);
}

// round 14
// speedup vs baseline: 1.2399x; 1.2399x over previous
#include <cuda_runtime.h>
#include <cuda_fp16.h>
#include <cstdint>

// Problem constants (match reference_code)
#define N0c 200000
#define N1c 50000
#define N2c 12500
#define N3c 3200
#define E0c 500000
#define E1c 125000
#define E2c 32000
#define DINc 128
#define DHc 256
#define DOUTc 128

// ---------------- scratch (static device globals; no allocations) ----------------
__device__ float g_mean[(size_t)N1c * DHc];
__device__ float g_h1[(size_t)N1c * DHc];
__device__ float g_h2[(size_t)N2c * DHc];
__device__ int g_deg0[N1c]; __device__ int g_off0[N1c + 1]; __device__ int g_cur0[N1c]; __device__ int g_esrc0[E0c];
__device__ int g_deg1[N2c]; __device__ int g_off1[N2c + 1]; __device__ int g_cur1[N2c]; __device__ int g_esrc1[E1c];
__device__ int g_deg2[N3c]; __device__ int g_off2[N3c + 1]; __device__ int g_cur2[N3c]; __device__ int g_esrc2[E2c];

// ---------------- CSR kernels (scan re-zeros deg for the next call;
// module-load zero-init covers the first invocation) ----------------
__global__ void hist_k(const int* __restrict__ dst, int* deg, int E) {
    int e = blockIdx.x * blockDim.x + threadIdx.x;
    if (e < E) atomicAdd(&deg[dst[e]], 1);
}

__global__ void scan_k(int* deg, int* off, int* cur, int n, int E) {
    const int T = 1024;
    __shared__ int wsum[32];
    int tid = threadIdx.x, lane = tid & 31, wid = tid >> 5;
    int chunk = (n + T - 1) / T;
    int beg = min(tid * chunk, n), end = min(beg + chunk, n);

    int sum = 0;
    for (int i = beg; i < end; i++) sum += deg[i];

    int s = sum;
    #pragma unroll
    for (int o = 1; o < 32; o <<= 1) {
        int t = __shfl_up_sync(0xffffffffu, s, o);
        if (lane >= o) s += t;
    }
    if (lane == 31) wsum[wid] = s;
    __syncthreads();
    if (wid == 0) {
        int ws = wsum[lane];
        #pragma unroll
        for (int o = 1; o < 32; o <<= 1) {
            int t = __shfl_up_sync(0xffffffffu, ws, o);
            if (lane >= o) ws += t;
        }
        wsum[lane] = ws;
    }
    __syncthreads();
    int excl = s - sum + ((wid > 0) ? wsum[wid - 1] : 0);

    int run = excl;
    for (int i = beg; i < end; i++) {
        int d = deg[i];
        off[i] = run;
        cur[i] = run;
        run += d;
        deg[i] = 0;
    }
    if (tid == 0) off[n] = E;
}

__global__ void bucket_k(const int* __restrict__ src, const int* __restrict__ dst,
                         int* cur, int* esrc, int E) {
    int e = blockIdx.x * blockDim.x + threadIdx.x;
    if (e < E) {
        int p = atomicAdd(&cur[dst[e]], 1);
        esrc[p] = src[e];
    }
}

// ---------------- aggregation: warp per target node (R2 2-edge unroll) ----------------
template <int D>
__global__ void aggregate_kernel(const float* __restrict__ X, float* __restrict__ mean,
                                 const int* __restrict__ off, const int* __restrict__ esrc,
                                 int n_tgt) {
    int w = (blockIdx.x * blockDim.x + threadIdx.x) >> 5;
    int lane = threadIdx.x & 31;
    if (w >= n_tgt) return;
    int beg = off[w], end = off[w + 1];
    float acc[D / 32];
    #pragma unroll
    for (int i = 0; i < D / 32; i++) acc[i] = 0.f;
    int e = beg;
    for (; e + 1 < end; e += 2) {
        int s0 = esrc[e], s1 = esrc[e + 1];
        const float4* r0 = (const float4*)(X + (size_t)s0 * D);
        const float4* r1 = (const float4*)(X + (size_t)s1 * D);
        #pragma unroll
        for (int i = 0; i < D / 128; i++) {
            float4 v0 = r0[lane + 32 * i];
            float4 v1 = r1[lane + 32 * i];
            acc[4 * i + 0] += v0.x + v1.x;
            acc[4 * i + 1] += v0.y + v1.y;
            acc[4 * i + 2] += v0.z + v1.z;
            acc[4 * i + 3] += v0.w + v1.w;
        }
    }
    if (e < end) {
        const float4* row = (const float4*)(X + (size_t)esrc[e] * D);
        #pragma unroll
        for (int i = 0; i < D / 128; i++) {
            float4 v = row[lane + 32 * i];
            acc[4 * i + 0] += v.x;
            acc[4 * i + 1] += v.y;
            acc[4 * i + 2] += v.z;
            acc[4 * i + 3] += v.w;
        }
    }
    float inv = 1.f / (float)max(end - beg, 1);
    float4* mrow = (float4*)(mean + (size_t)w * D);
    #pragma unroll
    for (int i = 0; i < D / 128; i++) {
        float4 o;
        o.x = acc[4 * i + 0] * inv;
        o.y = acc[4 * i + 1] * inv;
        o.z = acc[4 * i + 2] * inv;
        o.w = acc[4 * i + 3] * inv;
        mrow[lane + 32 * i] = o;
    }
}

// ---------------- fp16 + ldmatrix fused dual-A GEMM ----------------
// out = act( mean@Wl^T + Xtgt@Wr^T + b )
// Block 128x128, BK=32, 256 threads = 8 warps (2m x 4n), warp tile 64x32
// = 4x4 m16n8k16 f16 mma, fp32 accum. Fragments loaded with ldmatrix
// (LDK=40 halves -> all LDSM phases bank-conflict-free). cvt at STS time.

#define LDK 40   // halves per row (32 data + 8 pad); row stride 80 B

__device__ __forceinline__ uint32_t smem_u32(const void* p) {
    return (uint32_t)__cvta_generic_to_shared(p);
}

__global__ void __launch_bounds__(256) sage_gemm_f16(
    const float* __restrict__ A0, const float* __restrict__ A1,
    const float* __restrict__ Wl, const float* __restrict__ Wr,
    const float* __restrict__ bias, float* __restrict__ out,
    int M, int N, int D, int relu)
{
    __shared__ __half As[128 * LDK];
    __shared__ __half Bs[128 * LDK];

    int tid = threadIdx.x;
    int lane = tid & 31, wid = tid >> 5;
    int wm = wid & 1;        // 0..1  -> 64-row half
    int wn = wid >> 1;       // 0..3  -> 32-col strip
    int g = lane >> 2, t = lane & 3;

    int rowBase = blockIdx.x * 128, colBase = blockIdx.y * 128;

    float acc[4][4][4];
    #pragma unroll
    for (int i = 0; i < 4; i++)
        #pragma unroll
        for (int j = 0; j < 4; j++)
            #pragma unroll
            for (int r = 0; r < 4; r++) acc[i][j][r] = 0.f;

    int ldr = tid >> 3;          // 0..31 (row within 32-row chunk)
    int ldc = (tid & 7) * 4;     // 0,4,...,28 (k-half offset)

    // ldmatrix per-lane row/k offsets
    int lrowA = lane & 15;             // rows of the two 8x8 m-matrices
    int lkA   = (lane >> 4) << 3;      // 0 / 8: k-half offset (matrices 2,3)
    int lrowB = lane & 7;
    int lkB   = ((lane >> 3) & 1) << 3;

    const int NT = (2 * D) / 32;

    for (int it = 0; it < NT; it++) {
        int kt = it * 32;
        const float* A = (kt < D) ? A0 : A1;
        const float* W = (kt < D) ? Wl : Wr;
        int kk = (kt < D) ? kt : (kt - D);

        #pragma unroll
        for (int s = 0; s < 4; s++) {
            int r = ldr + s * 32;
            int grow = rowBase + r;
            float4 v = make_float4(0.f, 0.f, 0.f, 0.f);
            if (grow < M) v = *(const float4*)(A + (size_t)grow * D + kk + ldc);
            __half2 p0 = __floats2half2_rn(v.x, v.y);
            __half2 p1 = __floats2half2_rn(v.z, v.w);
            *(uint2*)&As[r * LDK + ldc] = make_uint2(*(uint32_t*)&p0, *(uint32_t*)&p1);

            float4 w = *(const float4*)(W + (size_t)(colBase + r) * D + kk + ldc);
            __half2 q0 = __floats2half2_rn(w.x, w.y);
            __half2 q1 = __floats2half2_rn(w.z, w.w);
            *(uint2*)&Bs[r * LDK + ldc] = make_uint2(*(uint32_t*)&q0, *(uint32_t*)&q1);
        }
        __syncthreads();

        #pragma unroll
        for (int ks = 0; ks < 32; ks += 16) {
            uint32_t af[4][4];
            #pragma unroll
            for (int mi = 0; mi < 4; mi++) {
                int m = wm * 64 + mi * 16;
                uint32_t addr = smem_u32(&As[(m + lrowA) * LDK + ks + lkA]);
                asm volatile(
                    "ldmatrix.sync.aligned.m8n8.x4.shared.b16 {%0,%1,%2,%3}, [%4];"
                    : "=r"(af[mi][0]), "=r"(af[mi][1]), "=r"(af[mi][2]), "=r"(af[mi][3])
                    : "r"(addr));
            }
            uint32_t bf[4][2];
            #pragma unroll
            for (int ni = 0; ni < 4; ni++) {
                int n = wn * 32 + ni * 8;
                uint32_t addr = smem_u32(&Bs[(n + lrowB) * LDK + ks + lkB]);
                asm volatile(
                    "ldmatrix.sync.aligned.m8n8.x2.shared.b16 {%0,%1}, [%2];"
                    : "=r"(bf[ni][0]), "=r"(bf[ni][1])
                    : "r"(addr));
            }
            #pragma unroll
            for (int mi = 0; mi < 4; mi++)
                #pragma unroll
                for (int ni = 0; ni < 4; ni++) {
                    asm volatile(
                        "mma.sync.aligned.m16n8k16.row.col.f32.f16.f16.f32 "
                        "{%0,%1,%2,%3}, {%4,%5,%6,%7}, {%8,%9}, {%0,%1,%2,%3};"
                        : "+f"(acc[mi][ni][0]), "+f"(acc[mi][ni][1]),
                          "+f"(acc[mi][ni][2]), "+f"(acc[mi][ni][3])
                        : "r"(af[mi][0]), "r"(af[mi][1]), "r"(af[mi][2]), "r"(af[mi][3]),
                          "r"(bf[ni][0]), "r"(bf[ni][1]));
                }
        }
        __syncthreads();
    }

    // epilogue: bias + optional relu
    #pragma unroll
    for (int mi = 0; mi < 4; mi++) {
        #pragma unroll
        for (int ni = 0; ni < 4; ni++) {
            int col = colBase + wn * 32 + ni * 8 + t * 2;
            float b0v = bias[col], b1v = bias[col + 1];
            int row0 = rowBase + wm * 64 + mi * 16 + g;
            if (row0 < M) {
                float2 o;
                o.x = acc[mi][ni][0] + b0v;
                o.y = acc[mi][ni][1] + b1v;
                if (relu) { o.x = fmaxf(o.x, 0.f); o.y = fmaxf(o.y, 0.f); }
                *(float2*)(out + (size_t)row0 * N + col) = o;
            }
            int row1 = row0 + 8;
            if (row1 < M) {
                float2 o;
                o.x = acc[mi][ni][2] + b0v;
                o.y = acc[mi][ni][3] + b1v;
                if (relu) { o.x = fmaxf(o.x, 0.f); o.y = fmaxf(o.y, 0.f); }
                *(float2*)(out + (size_t)row1 * N + col) = o;
            }
        }
    }
}

extern "C" void kernel_launch(void* const* d_in, const int* in_sizes, int n_in,
                              void* d_out, int out_size)
{
    const float* x    = (const float*)d_in[0];
    const int*   src0 = (const int*)d_in[1];
    const int*   dst0 = (const int*)d_in[2];
    const int*   src1 = (const int*)d_in[3];
    const int*   dst1 = (const int*)d_in[4];
    const int*   src2 = (const int*)d_in[5];
    const int*   dst2 = (const int*)d_in[6];
    const float* wl0  = (const float*)d_in[7];
    const float* wr0  = (const float*)d_in[8];
    const float* b0   = (const float*)d_in[9];
    const float* wl1  = (const float*)d_in[10];
    const float* wr1  = (const float*)d_in[11];
    const float* b1   = (const float*)d_in[12];
    const float* wl2  = (const float*)d_in[13];
    const float* wr2  = (const float*)d_in[14];
    const float* b2   = (const float*)d_in[15];
    float* out = (float*)d_out;

    float *h1, *h2, *mean;
    cudaGetSymbolAddress((void**)&h1, g_h1);
    cudaGetSymbolAddress((void**)&h2, g_h2);
    cudaGetSymbolAddress((void**)&mean, g_mean);
    int *deg0, *off0, *cur0, *es0, *deg1, *off1, *cur1, *es1, *deg2, *off2, *cur2, *es2;
    cudaGetSymbolAddress((void**)&deg0, g_deg0);
    cudaGetSymbolAddress((void**)&off0, g_off0);
    cudaGetSymbolAddress((void**)&cur0, g_cur0);
    cudaGetSymbolAddress((void**)&es0, g_esrc0);
    cudaGetSymbolAddress((void**)&deg1, g_deg1);
    cudaGetSymbolAddress((void**)&off1, g_off1);
    cudaGetSymbolAddress((void**)&cur1, g_cur1);
    cudaGetSymbolAddress((void**)&es1, g_esrc1);
    cudaGetSymbolAddress((void**)&deg2, g_deg2);
    cudaGetSymbolAddress((void**)&off2, g_off2);
    cudaGetSymbolAddress((void**)&cur2, g_cur2);
    cudaGetSymbolAddress((void**)&es2, g_esrc2);

    // Serial single stream. Launch order per layer: hist, scan, bucket, agg, gemm
    // (agg0 is the 4th app launch -> profiled by ncu)
    hist_k<<<(E0c + 255) / 256, 256>>>(dst0, deg0, E0c);
    scan_k<<<1, 1024>>>(deg0, off0, cur0, N1c, E0c);
    bucket_k<<<(E0c + 255) / 256, 256>>>(src0, dst0, cur0, es0, E0c);
    aggregate_kernel<128><<<(N1c * 32 + 255) / 256, 256>>>(x, mean, off0, es0, N1c);
    dim3 g0((N1c + 127) / 128, 2);
    sage_gemm_f16<<<g0, 256>>>(mean, x, wl0, wr0, b0, h1, N1c, DHc, DINc, 1);

    // Layer 1
    hist_k<<<(E1c + 255) / 256, 256>>>(dst1, deg1, E1c);
    scan_k<<<1, 1024>>>(deg1, off1, cur1, N2c, E1c);
    bucket_k<<<(E1c + 255) / 256, 256>>>(src1, dst1, cur1, es1, E1c);
    aggregate_kernel<256><<<(N2c * 32 + 255) / 256, 256>>>(h1, mean, off1, es1, N2c);
    dim3 g1((N2c + 127) / 128, 2);
    sage_gemm_f16<<<g1, 256>>>(mean, h1, wl1, wr1, b1, h2, N2c, DHc, DHc, 1);

    // Layer 2
    hist_k<<<(E2c + 255) / 256, 256>>>(dst2, deg2, E2c);
    scan_k<<<1, 1024>>>(deg2, off2, cur2, N3c, E2c);
    bucket_k<<<(E2c + 255) / 256, 256>>>(src2, dst2, cur2, es2, E2c);
    aggregate_kernel<256><<<(N3c * 32 + 255) / 256, 256>>>(h2, mean, off2, es2, N3c);
    dim3 g2((N3c + 127) / 128, 1);
    sage_gemm_f16<<<g2, 256>>>(mean, h2, wl2, wr2, b2, out, N3c, DOUTc, DHc, 0);
}

// round 15
// speedup vs baseline: 1.4262x; 1.1503x over previous
#include <cuda_runtime.h>
#include <cuda_fp16.h>
#include <cstdint>

// Problem constants (match reference_code)
#define N0c 200000
#define N1c 50000
#define N2c 12500
#define N3c 3200
#define E0c 500000
#define E1c 125000
#define E2c 32000
#define DINc 128
#define DHc 256
#define DOUTc 128

// ---------------- scratch (static device globals; no allocations) ----------------
__device__ __half g_mean[(size_t)N1c * DHc];     // fp16 mean buffer
__device__ __half g_h1[(size_t)N1c * DHc];       // fp16 layer outputs
__device__ __half g_h2[(size_t)N2c * DHc];
__device__ int g_deg0[N1c]; __device__ int g_off0[N1c + 1]; __device__ int g_cur0[N1c]; __device__ int g_esrc0[E0c];
__device__ int g_deg1[N2c]; __device__ int g_off1[N2c + 1]; __device__ int g_cur1[N2c]; __device__ int g_esrc1[E1c];
__device__ int g_deg2[N3c]; __device__ int g_off2[N3c + 1]; __device__ int g_cur2[N3c]; __device__ int g_esrc2[E2c];

// ---------------- batched CSR build (3 launches; scan re-zeros deg for replay;
// module-load zero-init covers the first invocation) ----------------
__global__ void hist3_kernel(const int* __restrict__ d0, const int* __restrict__ d1,
                             const int* __restrict__ d2) {
    int e = blockIdx.x * blockDim.x + threadIdx.x;
    if (e < E0c) atomicAdd(&g_deg0[d0[e]], 1);
    else if (e < E0c + E1c) atomicAdd(&g_deg1[d1[e - E0c]], 1);
    else if (e < E0c + E1c + E2c) atomicAdd(&g_deg2[d2[e - E0c - E1c]], 1);
}

__global__ void scan3_kernel() {
    const int T = 1024;
    __shared__ int wsum[32];
    int layer = blockIdx.x;
    int n = (layer == 0) ? N1c : (layer == 1) ? N2c : N3c;
    int E = (layer == 0) ? E0c : (layer == 1) ? E1c : E2c;
    int* deg = (layer == 0) ? g_deg0 : (layer == 1) ? g_deg1 : g_deg2;
    int* off = (layer == 0) ? g_off0 : (layer == 1) ? g_off1 : g_off2;
    int* cur = (layer == 0) ? g_cur0 : (layer == 1) ? g_cur1 : g_cur2;

    int tid = threadIdx.x, lane = tid & 31, wid = tid >> 5;
    int chunk = (n + T - 1) / T;
    int beg = min(tid * chunk, n), end = min(beg + chunk, n);

    int sum = 0;
    for (int i = beg; i < end; i++) sum += deg[i];

    int s = sum;
    #pragma unroll
    for (int o = 1; o < 32; o <<= 1) {
        int t = __shfl_up_sync(0xffffffffu, s, o);
        if (lane >= o) s += t;
    }
    if (lane == 31) wsum[wid] = s;
    __syncthreads();
    if (wid == 0) {
        int ws = wsum[lane];
        #pragma unroll
        for (int o = 1; o < 32; o <<= 1) {
            int t = __shfl_up_sync(0xffffffffu, ws, o);
            if (lane >= o) ws += t;
        }
        wsum[lane] = ws;
    }
    __syncthreads();
    int excl = s - sum + ((wid > 0) ? wsum[wid - 1] : 0);

    int run = excl;
    for (int i = beg; i < end; i++) {
        int d = deg[i];
        off[i] = run;
        cur[i] = run;
        run += d;
        deg[i] = 0;              // ready for next replay's hist
    }
    if (tid == 0) off[n] = E;
}

__global__ void bucket3_kernel(const int* __restrict__ s0, const int* __restrict__ d0,
                               const int* __restrict__ s1, const int* __restrict__ d1,
                               const int* __restrict__ s2, const int* __restrict__ d2) {
    int e = blockIdx.x * blockDim.x + threadIdx.x;
    if (e < E0c) {
        int p = atomicAdd(&g_cur0[d0[e]], 1);
        g_esrc0[p] = s0[e];
    } else if (e < E0c + E1c) {
        int i = e - E0c;
        int p = atomicAdd(&g_cur1[d1[i]], 1);
        g_esrc1[p] = s1[i];
    } else if (e < E0c + E1c + E2c) {
        int i = e - E0c - E1c;
        int p = atomicAdd(&g_cur2[d2[i]], 1);
        g_esrc2[p] = s2[i];
    }
}

// ---------------- aggregation (fp32 input -> fp16 mean): layer 0 ----------------
template <int D>
__global__ void aggregate_f32(const float* __restrict__ X, __half* __restrict__ mean,
                              const int* __restrict__ off, const int* __restrict__ esrc,
                              int n_tgt) {
    int w = (blockIdx.x * blockDim.x + threadIdx.x) >> 5;
    int lane = threadIdx.x & 31;
    if (w >= n_tgt) return;
    int beg = off[w], end = off[w + 1];
    float acc[D / 32];
    #pragma unroll
    for (int i = 0; i < D / 32; i++) acc[i] = 0.f;
    int e = beg;
    for (; e + 1 < end; e += 2) {
        int s0 = esrc[e], s1 = esrc[e + 1];
        const float4* r0 = (const float4*)(X + (size_t)s0 * D);
        const float4* r1 = (const float4*)(X + (size_t)s1 * D);
        #pragma unroll
        for (int i = 0; i < D / 128; i++) {
            float4 v0 = r0[lane + 32 * i];
            float4 v1 = r1[lane + 32 * i];
            acc[4 * i + 0] += v0.x + v1.x;
            acc[4 * i + 1] += v0.y + v1.y;
            acc[4 * i + 2] += v0.z + v1.z;
            acc[4 * i + 3] += v0.w + v1.w;
        }
    }
    if (e < end) {
        const float4* row = (const float4*)(X + (size_t)esrc[e] * D);
        #pragma unroll
        for (int i = 0; i < D / 128; i++) {
            float4 v = row[lane + 32 * i];
            acc[4 * i + 0] += v.x;
            acc[4 * i + 1] += v.y;
            acc[4 * i + 2] += v.z;
            acc[4 * i + 3] += v.w;
        }
    }
    float inv = 1.f / (float)max(end - beg, 1);
    uint2* mrow = (uint2*)(mean + (size_t)w * D);
    #pragma unroll
    for (int i = 0; i < D / 128; i++) {
        __half2 p0 = __floats2half2_rn(acc[4 * i + 0] * inv, acc[4 * i + 1] * inv);
        __half2 p1 = __floats2half2_rn(acc[4 * i + 2] * inv, acc[4 * i + 3] * inv);
        mrow[lane + 32 * i] = make_uint2(*(uint32_t*)&p0, *(uint32_t*)&p1);
    }
}

// ---------------- aggregation (fp16 input -> fp16 mean): layers 1,2 ----------------
template <int D>
__global__ void aggregate_f16(const __half* __restrict__ X, __half* __restrict__ mean,
                              const int* __restrict__ off, const int* __restrict__ esrc,
                              int n_tgt) {
    int w = (blockIdx.x * blockDim.x + threadIdx.x) >> 5;
    int lane = threadIdx.x & 31;
    if (w >= n_tgt) return;
    int beg = off[w], end = off[w + 1];
    float acc[D / 32];
    #pragma unroll
    for (int i = 0; i < D / 32; i++) acc[i] = 0.f;
    int e = beg;
    for (; e + 1 < end; e += 2) {
        int s0 = esrc[e], s1 = esrc[e + 1];
        const uint2* r0 = (const uint2*)(X + (size_t)s0 * D);
        const uint2* r1 = (const uint2*)(X + (size_t)s1 * D);
        #pragma unroll
        for (int i = 0; i < D / 128; i++) {
            uint2 u0 = r0[lane + 32 * i];
            uint2 u1 = r1[lane + 32 * i];
            float2 a0 = __half22float2(*(__half2*)&u0.x);
            float2 a1 = __half22float2(*(__half2*)&u0.y);
            float2 b0 = __half22float2(*(__half2*)&u1.x);
            float2 b1 = __half22float2(*(__half2*)&u1.y);
            acc[4 * i + 0] += a0.x + b0.x;
            acc[4 * i + 1] += a0.y + b0.y;
            acc[4 * i + 2] += a1.x + b1.x;
            acc[4 * i + 3] += a1.y + b1.y;
        }
    }
    if (e < end) {
        const uint2* r0 = (const uint2*)(X + (size_t)esrc[e] * D);
        #pragma unroll
        for (int i = 0; i < D / 128; i++) {
            uint2 u0 = r0[lane + 32 * i];
            float2 a0 = __half22float2(*(__half2*)&u0.x);
            float2 a1 = __half22float2(*(__half2*)&u0.y);
            acc[4 * i + 0] += a0.x;
            acc[4 * i + 1] += a0.y;
            acc[4 * i + 2] += a1.x;
            acc[4 * i + 3] += a1.y;
        }
    }
    float inv = 1.f / (float)max(end - beg, 1);
    uint2* mrow = (uint2*)(mean + (size_t)w * D);
    #pragma unroll
    for (int i = 0; i < D / 128; i++) {
        __half2 p0 = __floats2half2_rn(acc[4 * i + 0] * inv, acc[4 * i + 1] * inv);
        __half2 p1 = __floats2half2_rn(acc[4 * i + 2] * inv, acc[4 * i + 3] * inv);
        mrow[lane + 32 * i] = make_uint2(*(uint32_t*)&p0, *(uint32_t*)&p1);
    }
}

// ---------------- fp16 + ldmatrix fused dual-A GEMM ----------------
// out = act( mean@Wl^T + Xtgt@Wr^T + b ). Block 128x128, BK=32, 8 warps (2m x 4n),
// warp tile 64x32 = 4x4 m16n8k16, fp32 accum. A0 always fp16 (mean);
// A1 fp16 or fp32 (x on layer 0); out fp16 (h) or fp32 (final).

#define LDK 40   // halves per row (32 data + 8 pad); row stride 80 B

__device__ __forceinline__ uint32_t smem_u32(const void* p) {
    return (uint32_t)__cvta_generic_to_shared(p);
}

template <bool H>
__device__ __forceinline__ uint2 load4h(const void* base, size_t row, int D, int k, bool valid) {
    if (H) {
        if (!valid) return make_uint2(0, 0);
        return *(const uint2*)((const __half*)base + row * D + k);
    } else {
        float4 v = make_float4(0.f, 0.f, 0.f, 0.f);
        if (valid) v = *(const float4*)((const float*)base + row * D + k);
        __half2 p0 = __floats2half2_rn(v.x, v.y);
        __half2 p1 = __floats2half2_rn(v.z, v.w);
        return make_uint2(*(uint32_t*)&p0, *(uint32_t*)&p1);
    }
}

template <bool A1H, bool OUTH>
__global__ void __launch_bounds__(256) sage_gemm(
    const __half* __restrict__ A0, const void* __restrict__ A1,
    const float* __restrict__ Wl, const float* __restrict__ Wr,
    const float* __restrict__ bias, void* __restrict__ outv,
    int M, int N, int D, int relu)
{
    __shared__ __half As[128 * LDK];
    __shared__ __half Bs[128 * LDK];

    int tid = threadIdx.x;
    int lane = tid & 31, wid = tid >> 5;
    int wm = wid & 1;
    int wn = wid >> 1;
    int g = lane >> 2, t = lane & 3;

    int rowBase = blockIdx.x * 128, colBase = blockIdx.y * 128;

    float acc[4][4][4];
    #pragma unroll
    for (int i = 0; i < 4; i++)
        #pragma unroll
        for (int j = 0; j < 4; j++)
            #pragma unroll
            for (int r = 0; r < 4; r++) acc[i][j][r] = 0.f;

    int ldr = tid >> 3;
    int ldc = (tid & 7) * 4;

    int lrowA = lane & 15;
    int lkA   = (lane >> 4) << 3;
    int lrowB = lane & 7;
    int lkB   = ((lane >> 3) & 1) << 3;

    const int NT = (2 * D) / 32;

    for (int it = 0; it < NT; it++) {
        int kt = it * 32;
        bool first = (kt < D);
        const float* W = first ? Wl : Wr;
        int kk = first ? kt : (kt - D);

        #pragma unroll
        for (int s = 0; s < 4; s++) {
            int r = ldr + s * 32;
            int grow = rowBase + r;
            uint2 ua = first
                ? load4h<true>(A0, (size_t)grow, D, kk + ldc, grow < M)
                : load4h<A1H>(A1, (size_t)grow, D, kk + ldc, grow < M);
            *(uint2*)&As[r * LDK + ldc] = ua;

            float4 w = *(const float4*)(W + (size_t)(colBase + r) * D + kk + ldc);
            __half2 q0 = __floats2half2_rn(w.x, w.y);
            __half2 q1 = __floats2half2_rn(w.z, w.w);
            *(uint2*)&Bs[r * LDK + ldc] = make_uint2(*(uint32_t*)&q0, *(uint32_t*)&q1);
        }
        __syncthreads();

        #pragma unroll
        for (int ks = 0; ks < 32; ks += 16) {
            uint32_t af[4][4];
            #pragma unroll
            for (int mi = 0; mi < 4; mi++) {
                int m = wm * 64 + mi * 16;
                uint32_t addr = smem_u32(&As[(m + lrowA) * LDK + ks + lkA]);
                asm volatile(
                    "ldmatrix.sync.aligned.m8n8.x4.shared.b16 {%0,%1,%2,%3}, [%4];"
                    : "=r"(af[mi][0]), "=r"(af[mi][1]), "=r"(af[mi][2]), "=r"(af[mi][3])
                    : "r"(addr));
            }
            uint32_t bf[4][2];
            #pragma unroll
            for (int ni = 0; ni < 4; ni++) {
                int n = wn * 32 + ni * 8;
                uint32_t addr = smem_u32(&Bs[(n + lrowB) * LDK + ks + lkB]);
                asm volatile(
                    "ldmatrix.sync.aligned.m8n8.x2.shared.b16 {%0,%1}, [%2];"
                    : "=r"(bf[ni][0]), "=r"(bf[ni][1])
                    : "r"(addr));
            }
            #pragma unroll
            for (int mi = 0; mi < 4; mi++)
                #pragma unroll
                for (int ni = 0; ni < 4; ni++) {
                    asm volatile(
                        "mma.sync.aligned.m16n8k16.row.col.f32.f16.f16.f32 "
                        "{%0,%1,%2,%3}, {%4,%5,%6,%7}, {%8,%9}, {%0,%1,%2,%3};"
                        : "+f"(acc[mi][ni][0]), "+f"(acc[mi][ni][1]),
                          "+f"(acc[mi][ni][2]), "+f"(acc[mi][ni][3])
                        : "r"(af[mi][0]), "r"(af[mi][1]), "r"(af[mi][2]), "r"(af[mi][3]),
                          "r"(bf[ni][0]), "r"(bf[ni][1]));
                }
        }
        __syncthreads();
    }

    // epilogue: bias + optional relu; store fp16 (h) or fp32 (final out)
    #pragma unroll
    for (int mi = 0; mi < 4; mi++) {
        #pragma unroll
        for (int ni = 0; ni < 4; ni++) {
            int col = colBase + wn * 32 + ni * 8 + t * 2;
            float b0v = bias[col], b1v = bias[col + 1];
            #pragma unroll
            for (int h = 0; h < 2; h++) {
                int row = rowBase + wm * 64 + mi * 16 + g + 8 * h;
                if (row >= M) continue;
                float ox = acc[mi][ni][2 * h + 0] + b0v;
                float oy = acc[mi][ni][2 * h + 1] + b1v;
                if (relu) { ox = fmaxf(ox, 0.f); oy = fmaxf(oy, 0.f); }
                if (OUTH) {
                    __half2 p = __floats2half2_rn(ox, oy);
                    *(uint32_t*)((__half*)outv + (size_t)row * N + col) = *(uint32_t*)&p;
                } else {
                    *(float2*)((float*)outv + (size_t)row * N + col) = make_float2(ox, oy);
                }
            }
        }
    }
}

extern "C" void kernel_launch(void* const* d_in, const int* in_sizes, int n_in,
                              void* d_out, int out_size)
{
    const float* x    = (const float*)d_in[0];
    const int*   src0 = (const int*)d_in[1];
    const int*   dst0 = (const int*)d_in[2];
    const int*   src1 = (const int*)d_in[3];
    const int*   dst1 = (const int*)d_in[4];
    const int*   src2 = (const int*)d_in[5];
    const int*   dst2 = (const int*)d_in[6];
    const float* wl0  = (const float*)d_in[7];
    const float* wr0  = (const float*)d_in[8];
    const float* b0   = (const float*)d_in[9];
    const float* wl1  = (const float*)d_in[10];
    const float* wr1  = (const float*)d_in[11];
    const float* b1   = (const float*)d_in[12];
    const float* wl2  = (const float*)d_in[13];
    const float* wr2  = (const float*)d_in[14];
    const float* b2   = (const float*)d_in[15];
    float* out = (float*)d_out;

    __half *h1, *h2, *mean;
    cudaGetSymbolAddress((void**)&h1, g_h1);
    cudaGetSymbolAddress((void**)&h2, g_h2);
    cudaGetSymbolAddress((void**)&mean, g_mean);
    int *off0, *off1, *off2, *es0, *es1, *es2;
    cudaGetSymbolAddress((void**)&off0, g_off0);
    cudaGetSymbolAddress((void**)&off1, g_off1);
    cudaGetSymbolAddress((void**)&off2, g_off2);
    cudaGetSymbolAddress((void**)&es0, g_esrc0);
    cudaGetSymbolAddress((void**)&es1, g_esrc1);
    cudaGetSymbolAddress((void**)&es2, g_esrc2);

    // Batched CSR (3 launches). Launch order:
    // hist3(1) scan3(2) bucket3(3) agg0(4)<-profiled gemm0(5) ...
    const int ETOT = E0c + E1c + E2c;
    hist3_kernel<<<(ETOT + 255) / 256, 256>>>(dst0, dst1, dst2);
    scan3_kernel<<<3, 1024>>>();
    bucket3_kernel<<<(ETOT + 255) / 256, 256>>>(src0, dst0, src1, dst1, src2, dst2);

    // Layer 0: x (fp32) -> h1 (fp16), relu
    aggregate_f32<128><<<(N1c * 32 + 255) / 256, 256>>>(x, mean, off0, es0, N1c);
    dim3 g0((N1c + 127) / 128, 2);
    sage_gemm<false, true><<<g0, 256>>>(mean, x, wl0, wr0, b0, h1, N1c, DHc, DINc, 1);

    // Layer 1: h1 (fp16) -> h2 (fp16), relu
    aggregate_f16<256><<<(N2c * 32 + 255) / 256, 256>>>(h1, mean, off1, es1, N2c);
    dim3 g1((N2c + 127) / 128, 2);
    sage_gemm<true, true><<<g1, 256>>>(mean, h1, wl1, wr1, b1, h2, N2c, DHc, DHc, 1);

    // Layer 2: h2 (fp16) -> out (fp32), no relu
    aggregate_f16<256><<<(N3c * 32 + 255) / 256, 256>>>(h2, mean, off2, es2, N3c);
    dim3 g2((N3c + 127) / 128, 1);
    sage_gemm<true, false><<<g2, 256>>>(mean, h2, wl2, wr2, b2, out, N3c, DOUTc, DHc, 0);
}